// round 13
// baseline (speedup 1.0000x reference)
#include <cuda_runtime.h>
#include <cuda_fp16.h>
#include <math.h>
#include <stdint.h>

#define BB 8
#define CC 512
#define DD 64
#define HWN 2304  // 48*48

// ---------------- scratch (static device globals; no allocation) ----------------
__device__ __half h_qryT[(size_t)BB*HWN*CC];   // [b][n][c]
__device__ __half h_sptT[(size_t)BB*HWN*CC];
__device__ __half h_wq [DD*CC];
__device__ __half h_wk [DD*CC];
__device__ __half h_wv1[CC*CC];
__device__ __half h_wv2[CC*CC];
__device__ __half h_cawq[CC*CC];
__device__ __half h_cawk[CC*CC];
__device__ __half h_cawv[CC*CC];
__device__ __half h_cawo[CC*CC];
__device__ __half h_q  [(size_t)BB*HWN*DD];
__device__ __half h_kt [(size_t)BB*HWN*DD];
__device__ float  g_scores[(size_t)BB*HWN*HWN];
__device__ __half h_S  [(size_t)BB*HWN*HWN];
__device__ __half h_ST [(size_t)BB*HWN*HWN];
__device__ __half h_v1 [(size_t)BB*CC*HWN];    // [b][c][n]
__device__ __half h_v2 [(size_t)BB*CC*HWN];
__device__ __half h_x1 [(size_t)BB*HWN*CC];    // [b][m][c]
__device__ __half h_x2 [(size_t)BB*HWN*CC];
__device__ __half h_q2 [(size_t)BB*HWN*CC];
__device__ __half h_k2 [(size_t)BB*HWN*CC];
__device__ __half h_v2fT[(size_t)BB*CC*HWN];   // [b][c][m]
__device__ float  g_w   [BB*HWN];
__device__ float  g_msum[BB];
__device__ float  g_pmid[BB*CC];
__device__ float  g_proto[BB*CC];
__device__ float  g_qp [BB*CC];
__device__ float  g_kp [BB*CC];
__device__ float  g_vp [BB*CC];
__device__ float  g_aw [BB];

// ======================= helpers =======================
__device__ __forceinline__ uint32_t smem_u32(const void* p) {
    uint32_t a;
    asm("{ .reg .u64 t; cvta.to.shared.u64 t, %1; cvt.u32.u64 %0, t; }" : "=r"(a) : "l"(p));
    return a;
}
__device__ __forceinline__ void cpa16(uint32_t dst, const void* src, int sz) {
    asm volatile("cp.async.ca.shared.global [%0], [%1], 16, %2;\n"
                 :: "r"(dst), "l"(src), "r"(sz));
}
#define CPA_COMMIT() asm volatile("cp.async.commit_group;\n" ::: "memory")
#define CPA_WAIT1()  asm volatile("cp.async.wait_group 1;\n" ::: "memory")
#define CPA_WAIT0()  asm volatile("cp.async.wait_group 0;\n" ::: "memory")

// ---------------- fp16 tensor-core GEMM, cp.async + ldmatrix --------------------
// C[i,j] = alpha*sum_k A[i][k]*B[j][k] (+bias)(+res). A,B fp16 row-major k-contig.
// Block tile 128x128, K-tile 32, 2 stages. 8 warps: 2(M) x 4(N), warp tile 64x32.
// Optional second operand set (A2,B2,C2,bias2): used when blockIdx.z >= BB
// (merges two same-shape independent GEMMs into one launch).
#define LDS_ROW 40   // 32 + 8 pad halves = 80B; ldmatrix rows hit disjoint bank quads

template <bool OUT_HALF>
__global__ __launch_bounds__(256, 2)
void hgemm2(int M, int N, int K,
            const __half* __restrict__ A, int lda, long bsA,
            const __half* __restrict__ B, int ldb, long bsB,
            void* __restrict__ Cv, int ldc, long bsC,
            const float* __restrict__ bias, int bias_mode,   // 0 none, 1 per-col(j), 2 per-row(i)
            const float* __restrict__ alpha_ptr, float alpha_const,
            const __half* __restrict__ Rm, int ldr, long bsR,
            const __half* A2, const __half* B2, void* Cv2, const float* bias2)
{
    __shared__ __half As[2][128][LDS_ROW];
    __shared__ __half Bs[2][128][LDS_ROW];

    int bz = blockIdx.z;
    const __half* Ap = A;
    const __half* Bp = B;
    void* Cp = Cv;
    const float* biasp = bias;
    if (A2 != nullptr && bz >= BB) {
        bz -= BB;
        Ap = A2; Bp = B2; Cp = Cv2; biasp = bias2;
    }
    Ap += (long)bz * bsA;
    Bp += (long)bz * bsB;
    if (Rm) Rm += (long)bz * bsR;

    int i0 = blockIdx.y * 128, j0 = blockIdx.x * 128;
    int tid = threadIdx.x;
    int lane = tid & 31, wid = tid >> 5;
    int warp_m = (wid & 1) * 64;
    int warp_n = (wid >> 1) * 32;
    int g = lane >> 2;        // 0..7
    int tg = lane & 3;        // 0..3

    uint32_t sA = smem_u32(&As[0][0][0]);
    uint32_t sB = smem_u32(&Bs[0][0][0]);
    const uint32_t stageBytes = 128 * LDS_ROW * 2;

    // ldmatrix per-lane source rows/cols (within the warp tile)
    int lm_arow = warp_m + (lane & 7) + 8 * ((lane >> 3) & 1);
    int lm_acol = 8 * ((lane >> 4) & 1);
    int lm_brow = warp_n + (lane & 7) + 8 * ((lane >> 4) & 1);
    int lm_bcol = 8 * ((lane >> 3) & 1);

    // per-thread copy tasks: 512 chunks per operand per stage, 2 per thread
    int crow = tid >> 2;          // 0..63 -> two rows: crow, crow+64
    int cch  = tid & 3;           // chunk 0..3 (16B each)

    auto load_tile = [&](int st, int kt) {
        int k0 = kt * 32;
#pragma unroll
        for (int h = 0; h < 2; h++) {
            int row = crow + h * 64;
            uint32_t off = (uint32_t)(row * LDS_ROW + cch * 8) * 2;
            cpa16(sA + st * stageBytes + off,
                  Ap + (long)(i0 + row) * lda + k0 + cch * 8, 16);
            int gj = j0 + row;
            cpa16(sB + st * stageBytes + off,
                  Bp + (long)gj * ldb + k0 + cch * 8, (gj < N) ? 16 : 0);
        }
    };

    float acc[4][4][4];
#pragma unroll
    for (int a = 0; a < 4; a++)
#pragma unroll
        for (int b = 0; b < 4; b++)
#pragma unroll
            for (int c = 0; c < 4; c++) acc[a][b][c] = 0.f;

    int T = K / 32;
    load_tile(0, 0);
    CPA_COMMIT();

    for (int kt = 0; kt < T; kt++) {
        int st = kt & 1;
        if (kt + 1 < T) {
            load_tile(st ^ 1, kt + 1);
            CPA_COMMIT();
            CPA_WAIT1();
        } else {
            CPA_WAIT0();
        }
        __syncthreads();

        uint32_t sAst = sA + st * stageBytes;
        uint32_t sBst = sB + st * stageBytes;
#pragma unroll
        for (int ks = 0; ks < 2; ks++) {
            int kb = ks * 16;
            uint32_t a[4][4];
#pragma unroll
            for (int mt = 0; mt < 4; mt++) {
                uint32_t addr = sAst +
                    (uint32_t)((lm_arow + mt * 16) * LDS_ROW + kb + lm_acol) * 2;
                asm volatile("ldmatrix.sync.aligned.m8n8.x4.shared.b16 {%0,%1,%2,%3}, [%4];"
                    : "=r"(a[mt][0]), "=r"(a[mt][1]), "=r"(a[mt][2]), "=r"(a[mt][3])
                    : "r"(addr));
            }
            uint32_t b[4][2];
#pragma unroll
            for (int np = 0; np < 2; np++) {
                uint32_t addr = sBst +
                    (uint32_t)((lm_brow + np * 16) * LDS_ROW + kb + lm_bcol) * 2;
                asm volatile("ldmatrix.sync.aligned.m8n8.x4.shared.b16 {%0,%1,%2,%3}, [%4];"
                    : "=r"(b[2 * np][0]), "=r"(b[2 * np][1]),
                      "=r"(b[2 * np + 1][0]), "=r"(b[2 * np + 1][1])
                    : "r"(addr));
            }
#pragma unroll
            for (int mt = 0; mt < 4; mt++)
#pragma unroll
                for (int nt = 0; nt < 4; nt++) {
                    asm volatile(
                        "mma.sync.aligned.m16n8k16.row.col.f32.f16.f16.f32 "
                        "{%0,%1,%2,%3}, {%4,%5,%6,%7}, {%8,%9}, {%0,%1,%2,%3};\n"
                        : "+f"(acc[mt][nt][0]), "+f"(acc[mt][nt][1]),
                          "+f"(acc[mt][nt][2]), "+f"(acc[mt][nt][3])
                        : "r"(a[mt][0]), "r"(a[mt][1]), "r"(a[mt][2]), "r"(a[mt][3]),
                          "r"(b[nt][0]), "r"(b[nt][1]));
                }
        }
        __syncthreads();
    }

    float alpha = alpha_const;
    if (alpha_ptr) alpha *= *alpha_ptr;

    float*  Cf = (float*)Cp;
    __half* Ch = (__half*)Cp;
    if (OUT_HALF) Ch += (long)bz * bsC; else Cf += (long)bz * bsC;

#pragma unroll
    for (int mt = 0; mt < 4; mt++) {
#pragma unroll
        for (int nt = 0; nt < 4; nt++) {
            int gj = j0 + warp_n + nt * 8 + tg * 2;
            if (gj >= N) continue;
#pragma unroll
            for (int half_row = 0; half_row < 2; half_row++) {
                int gi = i0 + warp_m + mt * 16 + g + half_row * 8;
                float v0 = alpha * acc[mt][nt][half_row * 2];
                float v1 = alpha * acc[mt][nt][half_row * 2 + 1];
                if (bias_mode == 1) { v0 += biasp[gj]; v1 += biasp[gj + 1]; }
                else if (bias_mode == 2) { float bb = biasp[gi]; v0 += bb; v1 += bb; }
                if (Rm) {
                    uint32_t rr = *(const uint32_t*)(Rm + (long)gi * ldr + gj);
                    __half2 rh = *(__half2*)&rr;
                    v0 += __half2float(rh.x);
                    v1 += __half2float(rh.y);
                }
                if (OUT_HALF) {
                    __half2 o = __floats2half2_rn(v0, v1);
                    *(uint32_t*)(Ch + (long)gi * ldc + gj) = *(uint32_t*)&o;
                } else {
                    *(float2*)(Cf + (long)gi * ldc + gj) = make_float2(v0, v1);
                }
            }
        }
    }
}

// ---------------- all weights fp32 -> fp16 in one launch ----------------
__global__ void w2h_all(const float* s0, const float* s1, const float* s2, const float* s3,
                        const float* s4, const float* s5, const float* s6, const float* s7,
                        __half* d0, __half* d1, __half* d2, __half* d3,
                        __half* d4, __half* d5, __half* d6, __half* d7)
{
    int which = blockIdx.y;
    const float* s; __half* d; int n;
    switch (which) {
        case 0: s = s0; d = d0; n = DD * CC; break;
        case 1: s = s1; d = d1; n = DD * CC; break;
        case 2: s = s2; d = d2; n = CC * CC; break;
        case 3: s = s3; d = d3; n = CC * CC; break;
        case 4: s = s4; d = d4; n = CC * CC; break;
        case 5: s = s5; d = d5; n = CC * CC; break;
        case 6: s = s6; d = d6; n = CC * CC; break;
        default: s = s7; d = d7; n = CC * CC; break;
    }
    int i = blockIdx.x * 1024 + threadIdx.x * 4;
    if (i + 3 < n) {
        float4 f = *(const float4*)(s + i);
        __half2 a = __floats2half2_rn(f.x, f.y);
        __half2 b = __floats2half2_rn(f.z, f.w);
        *(uint2*)(d + i) = make_uint2(*(uint32_t*)&a, *(uint32_t*)&b);
    }
}

// ---------------- transpose+convert: fp32 [C][HWN] -> fp16 [HWN][C], per batch ----
__global__ void tcvt_kernel(const float* __restrict__ src, __half* __restrict__ dst)
{
    __shared__ float tile[32][33];
    int b = blockIdx.z;
    int n0 = blockIdx.x * 32, c0 = blockIdx.y * 32;
    int tx = threadIdx.x, ty = threadIdx.y;  // (32, 8)
    const float* s = src + (long)b * CC * HWN;
    __half* d = dst + (long)b * HWN * CC;
#pragma unroll
    for (int i = 0; i < 4; i++)
        tile[ty + 8 * i][tx] = s[(long)(c0 + ty + 8 * i) * HWN + n0 + tx];
    __syncthreads();
#pragma unroll
    for (int i = 0; i < 4; i++)
        d[(long)(n0 + ty + 8 * i) * CC + c0 + tx] = __float2half(tile[tx][ty + 8 * i]);
}

// ---------------- fp16 transpose [HWN][HWN] per batch ----------------
__global__ void th_kernel(const __half* __restrict__ src, __half* __restrict__ dst)
{
    __shared__ __half tile[32][33];
    int b = blockIdx.z;
    int u0 = blockIdx.y * 32, v0 = blockIdx.x * 32;
    int tx = threadIdx.x, ty = threadIdx.y;  // (32, 8)
    const __half* s = src + (long)b * HWN * HWN;
    __half* d = dst + (long)b * HWN * HWN;
#pragma unroll
    for (int i = 0; i < 4; i++)
        tile[ty + 8 * i][tx] = s[(long)(u0 + ty + 8 * i) * HWN + v0 + tx];
    __syncthreads();
#pragma unroll
    for (int i = 0; i < 4; i++)
        d[(long)(v0 + ty + 8 * i) * HWN + u0 + tx] = tile[tx][ty + 8 * i];
}

// ---------------- row softmax over 2304 cols: fp32 in -> fp16 out ----------------
__global__ void softmax_h(const float* __restrict__ in, __half* __restrict__ out)
{
    long row = blockIdx.x;
    const float* p = in + row * (long)HWN;
    __half* o = out + row * (long)HWN;
    int t = threadIdx.x;
    float v[9];
    float mx = -1e30f;
#pragma unroll
    for (int i = 0; i < 9; i++) { v[i] = p[t + 256 * i]; mx = fmaxf(mx, v[i]); }

    __shared__ float red[256];
    red[t] = mx; __syncthreads();
    for (int s = 128; s > 0; s >>= 1) { if (t < s) red[t] = fmaxf(red[t], red[t + s]); __syncthreads(); }
    mx = red[0]; __syncthreads();

    float sm = 0.f;
#pragma unroll
    for (int i = 0; i < 9; i++) { v[i] = expf(v[i] - mx); sm += v[i]; }
    red[t] = sm; __syncthreads();
    for (int s = 128; s > 0; s >>= 1) { if (t < s) red[t] += red[t + s]; __syncthreads(); }
    float inv = 1.f / red[0];
#pragma unroll
    for (int i = 0; i < 9; i++) o[t + 256 * i] = __float2half(v[i] * inv);
}

// ---------------- w[b][m] = sum_n mask[b][n]*S2[b][n][m]; msum[b] = sum_n mask ----
__global__ void colw_kernel(const __half* __restrict__ S2, const float* __restrict__ mask,
                            float* __restrict__ w, float* __restrict__ msum)
{
    int b = blockIdx.y;
    int m0 = blockIdx.x * 256;            // 9 blocks of 256 columns
    int t = threadIdx.x;                  // 128 threads, half2 each
    const __half2* s = (const __half2*)(S2 + (long)b * HWN * HWN + m0) + t;
    const float* mp = mask + (long)b * HWN;
    float a0 = 0.f, a1 = 0.f, ms = 0.f;
    for (int n = 0; n < HWN; n += 4) {
#pragma unroll
        for (int u = 0; u < 4; u++) {
            float mk = mp[n + u];
            float2 f = __half22float2(s[(long)(n + u) * (HWN / 2)]);
            a0 += mk * f.x;
            a1 += mk * f.y;
            ms += mk;
        }
    }
    w[b * HWN + m0 + 2 * t]     = a0;
    w[b * HWN + m0 + 2 * t + 1] = a1;
    if (blockIdx.x == 0 && t == 0) msum[b] = ms;
}

// ---------------- pmid[b][c] = sum_m w[b][m]*v2fT[b][c][m] ----------------
__global__ void pooledmid_kernel(const float* __restrict__ w, const __half* __restrict__ v2fT,
                                 float* __restrict__ pmid)
{
    int b = blockIdx.y;
    int warp = threadIdx.x >> 5, lane = threadIdx.x & 31;
    int c = blockIdx.x * 8 + warp;
    const float* wb = w + b * HWN;
    const __half* vb = v2fT + (long)b * CC * HWN + (long)c * HWN;
    float acc = 0.f;
    for (int m = lane * 2; m < HWN; m += 64) {
        float2 f = __half22float2(*(const __half2*)(vb + m));
        acc += wb[m] * f.x + wb[m + 1] * f.y;
    }
#pragma unroll
    for (int o = 16; o > 0; o >>= 1) acc += __shfl_xor_sync(0xFFFFFFFFu, acc, o);
    if (lane == 0) pmid[b * CC + c] = acc;
}

// ---------------- proto[b][c2] = (pmid[b]·wo[c2] + bo[c2]*msum[b]) / (msum[b]+1e-5) ----
__global__ void proto_proj(const float* __restrict__ pmid, const float* __restrict__ msum,
                           const float* __restrict__ wo, const float* __restrict__ bo,
                           float* __restrict__ proto)
{
    int b = blockIdx.y;
    int warp = threadIdx.x >> 5, lane = threadIdx.x & 31;
    int c2 = blockIdx.x * 8 + warp;
    const float* pm = pmid + b * CC;
    const float* wr = wo + (long)c2 * CC;
    float acc = 0.f;
    for (int c = lane; c < CC; c += 32) acc += pm[c] * wr[c];
#pragma unroll
    for (int o = 16; o > 0; o >>= 1) acc += __shfl_xor_sync(0xFFFFFFFFu, acc, o);
    if (lane == 0) {
        float S = msum[b] + 1e-5f;
        proto[b * CC + c2] = (acc + bo[c2] * msum[b]) / S;
    }
}

// ---------------- pf projections ----------------
__global__ void pf_gemv(const float* __restrict__ proto,
                        const float* __restrict__ wq, const float* __restrict__ bq,
                        const float* __restrict__ wk, const float* __restrict__ bk,
                        const float* __restrict__ wv, const float* __restrict__ bv,
                        float* __restrict__ qp, float* __restrict__ kp, float* __restrict__ vp)
{
    int b = blockIdx.z, which = blockIdx.y;
    const float* W    = (which == 0) ? wq : (which == 1) ? wk : wv;
    const float* bias = (which == 0) ? bq : (which == 1) ? bk : bv;
    float* out        = (which == 0) ? qp : (which == 1) ? kp : vp;
    int warp = threadIdx.x >> 5, lane = threadIdx.x & 31;
    int c2 = blockIdx.x * 8 + warp;
    const float* pr = proto + b * CC;
    const float* wr = W + (long)c2 * CC;
    float acc = 0.f;
    for (int c = lane; c < CC; c += 32) acc += pr[c] * wr[c];
#pragma unroll
    for (int o = 16; o > 0; o >>= 1) acc += __shfl_xor_sync(0xFFFFFFFFu, acc, o);
    if (lane == 0) out[b * CC + c2] = acc + bias[c2];
}

__global__ void aw_kernel(const float* __restrict__ qp, const float* __restrict__ kp,
                          float* __restrict__ aw)
{
    int b = blockIdx.x, t = threadIdx.x;
    float acc = 0.f;
    for (int c = t; c < CC; c += 256) acc += qp[b * CC + c] * kp[b * CC + c];
    __shared__ float red[256];
    red[t] = acc; __syncthreads();
    for (int s = 128; s > 0; s >>= 1) { if (t < s) red[t] += red[t + s]; __syncthreads(); }
    if (t == 0) aw[b] = red[0];
}

__global__ void final_kernel(const float* __restrict__ aw, const float* __restrict__ vp,
                             float* __restrict__ out, int out_size)
{
    int c = threadIdx.x;
    float a[BB];
    float mx = -1e30f;
#pragma unroll
    for (int b = 0; b < BB; b++) { a[b] = aw[b]; mx = fmaxf(mx, a[b]); }
    float s = 0.f;
#pragma unroll
    for (int b = 0; b < BB; b++) { a[b] = expf(a[b] - mx); s += a[b]; }
    float inv = 1.f / s;
    float f = 0.f;
#pragma unroll
    for (int b = 0; b < BB; b++) f += a[b] * inv * vp[b * CC + c];
    if (c < out_size) out[c] = f;
}

// ---------------------------------------------------------------------------------------------
extern "C" void kernel_launch(void* const* d_in, const int* in_sizes, int n_in,
                              void* d_out, int out_size)
{
    const float* qry   = (const float*)d_in[0];
    const float* spt   = (const float*)d_in[1];
    const float* mask  = (const float*)d_in[2];
    const float* w_wq  = (const float*)d_in[3];
    const float* b_wq  = (const float*)d_in[4];
    const float* w_wk  = (const float*)d_in[5];
    const float* b_wk  = (const float*)d_in[6];
    const float* w_wv1 = (const float*)d_in[7];
    const float* b_wv1 = (const float*)d_in[8];
    const float* w_wv2 = (const float*)d_in[9];
    const float* b_wv2 = (const float*)d_in[10];
    const float* gamma1 = (const float*)d_in[11];
    const float* gamma2 = (const float*)d_in[12];
    const float* ca_wq = (const float*)d_in[13];
    const float* ca_bq = (const float*)d_in[14];
    const float* ca_wk = (const float*)d_in[15];
    const float* ca_bk = (const float*)d_in[16];
    const float* ca_wv = (const float*)d_in[17];
    const float* ca_bv = (const float*)d_in[18];
    const float* ca_wo = (const float*)d_in[19];
    const float* ca_bo = (const float*)d_in[20];
    const float* pf_wq = (const float*)d_in[21];
    const float* pf_bq = (const float*)d_in[22];
    const float* pf_wk = (const float*)d_in[23];
    const float* pf_bk = (const float*)d_in[24];
    const float* pf_wv = (const float*)d_in[25];
    const float* pf_bv = (const float*)d_in[26];

    __half *pqT, *psT, *pwq, *pwk, *pwv1, *pwv2, *pcq, *pck, *pcv, *pco;
    __half *pq, *pkt, *pS, *pST, *pv1, *pv2, *px1, *px2, *pq2, *pk2, *pv2fT;
    float *pscores, *pw, *pmsum, *ppmid, *pproto, *pqp, *pkp, *pvp, *paw;
    cudaGetSymbolAddress((void**)&pqT, h_qryT);
    cudaGetSymbolAddress((void**)&psT, h_sptT);
    cudaGetSymbolAddress((void**)&pwq, h_wq);
    cudaGetSymbolAddress((void**)&pwk, h_wk);
    cudaGetSymbolAddress((void**)&pwv1, h_wv1);
    cudaGetSymbolAddress((void**)&pwv2, h_wv2);
    cudaGetSymbolAddress((void**)&pcq, h_cawq);
    cudaGetSymbolAddress((void**)&pck, h_cawk);
    cudaGetSymbolAddress((void**)&pcv, h_cawv);
    cudaGetSymbolAddress((void**)&pco, h_cawo);
    cudaGetSymbolAddress((void**)&pq, h_q);
    cudaGetSymbolAddress((void**)&pkt, h_kt);
    cudaGetSymbolAddress((void**)&pscores, g_scores);
    cudaGetSymbolAddress((void**)&pS, h_S);
    cudaGetSymbolAddress((void**)&pST, h_ST);
    cudaGetSymbolAddress((void**)&pv1, h_v1);
    cudaGetSymbolAddress((void**)&pv2, h_v2);
    cudaGetSymbolAddress((void**)&px1, h_x1);
    cudaGetSymbolAddress((void**)&px2, h_x2);
    cudaGetSymbolAddress((void**)&pq2, h_q2);
    cudaGetSymbolAddress((void**)&pk2, h_k2);
    cudaGetSymbolAddress((void**)&pv2fT, h_v2fT);
    cudaGetSymbolAddress((void**)&pw, g_w);
    cudaGetSymbolAddress((void**)&pmsum, g_msum);
    cudaGetSymbolAddress((void**)&ppmid, g_pmid);
    cudaGetSymbolAddress((void**)&pproto, g_proto);
    cudaGetSymbolAddress((void**)&pqp, g_qp);
    cudaGetSymbolAddress((void**)&pkp, g_kp);
    cudaGetSymbolAddress((void**)&pvp, g_vp);
    cudaGetSymbolAddress((void**)&paw, g_aw);

    const long NC   = (long)HWN * CC;     // 2304*512
    const long ND   = (long)HWN * DD;
    const long NN   = (long)HWN * HWN;
    dim3 blk(256);
    const float inv_sqrt_c = 0.044194173824159216f;

    // 0a) all weights -> fp16, one launch
    w2h_all<<<dim3((CC * CC) / 1024, 8), 256>>>(
        w_wq, w_wk, w_wv1, w_wv2, ca_wq, ca_wk, ca_wv, ca_wo,
        pwq, pwk, pwv1, pwv2, pcq, pck, pcv, pco);
    // 0b) qry/spt -> fp16 transposed [n][c]
    tcvt_kernel<<<dim3(HWN / 32, CC / 32, BB), dim3(32, 8)>>>(qry, pqT);
    tcvt_kernel<<<dim3(HWN / 32, CC / 32, BB), dim3(32, 8)>>>(spt, psT);

    // 1+2) q/kt merged: q[n][d] = qryT·wq^T + b ; kt[n][d] = sptT·wk^T + b
    hgemm2<true><<<dim3(1, 18, 2 * BB), blk>>>(HWN, DD, CC,
        pqT, CC, NC,  pwq, CC, 0,  pq, DD, ND,  b_wq, 1, nullptr, 1.f, nullptr, 0, 0,
        psT, pwk, pkt, b_wk);
    // 3) scores1[n][m] = q·kt^T   (M=N=2304,K=64)
    hgemm2<false><<<dim3(18, 18, BB), blk>>>(HWN, HWN, DD,
        pq, DD, ND,  pkt, DD, ND,  pscores, HWN, NN,  nullptr, 0, nullptr, 1.f, nullptr, 0, 0,
        nullptr, nullptr, nullptr, nullptr);
    // 4) softmax -> S fp16 ; transpose -> ST
    softmax_h<<<BB * HWN, 256>>>(pscores, pS);
    th_kernel<<<dim3(HWN / 32, HWN / 32, BB), dim3(32, 8)>>>(pS, pST);
    // 5+6) v1/v2 merged: v1[c][n] = wv1·qry + b ; v2[c][n] = wv2·spt + b (bias per-row c)
    hgemm2<true><<<dim3(18, 4, 2 * BB), blk>>>(CC, HWN, CC,
        pwv1, CC, 0,  pqT, CC, NC,  pv1, HWN, (long)CC * HWN,  b_wv1, 2, nullptr, 1.f, nullptr, 0, 0,
        pwv2, psT, pv2, b_wv2);
    // 7) x1[m][c] = gamma1·sum_n S[m][n]·v1[c][n] + qryT[m][c]  (M=2304,N=512,K=2304)
    hgemm2<true><<<dim3(4, 18, BB), blk>>>(HWN, CC, HWN,
        pS, HWN, NN,  pv1, HWN, (long)CC * HWN,  px1, CC, NC,
        nullptr, 0, gamma1, 1.f, pqT, CC, NC,
        nullptr, nullptr, nullptr, nullptr);
    // 8) x2[m][c] = gamma2·sum_n ST[m][n]·v2[c][n] + sptT[m][c]
    hgemm2<true><<<dim3(4, 18, BB), blk>>>(HWN, CC, HWN,
        pST, HWN, NN,  pv2, HWN, (long)CC * HWN,  px2, CC, NC,
        nullptr, 0, gamma2, 1.f, psT, CC, NC,
        nullptr, nullptr, nullptr, nullptr);
    // 9+10) q2/k2 merged: q2 = x1·ca_wq^T + b ; k2 = x2·ca_wk^T + b  (M=2304,N=512,K=512)
    hgemm2<true><<<dim3(4, 18, 2 * BB), blk>>>(HWN, CC, CC,
        px1, CC, NC,  pcq, CC, 0,  pq2, CC, NC,  ca_bq, 1, nullptr, 1.f, nullptr, 0, 0,
        px2, pck, pk2, ca_bk);
    // 11) v2fT[c][m] = ca_wv·x2^T + b  (M=512,N=2304,K=512), bias per-row c
    hgemm2<true><<<dim3(18, 4, BB), blk>>>(CC, HWN, CC,
        pcv, CC, 0,  px2, CC, NC,  pv2fT, HWN, (long)CC * HWN,  ca_bv, 2, nullptr, 1.f, nullptr, 0, 0,
        nullptr, nullptr, nullptr, nullptr);
    // 12) scores2[n][m] = q2·k2^T /sqrt(C)  (M=N=2304,K=512)
    hgemm2<false><<<dim3(18, 18, BB), blk>>>(HWN, HWN, CC,
        pq2, CC, NC,  pk2, CC, NC,  pscores, HWN, NN,  nullptr, 0, nullptr, inv_sqrt_c, nullptr, 0, 0,
        nullptr, nullptr, nullptr, nullptr);
    // 13) softmax -> S2 fp16 (reuse h_S)
    softmax_h<<<BB * HWN, 256>>>(pscores, pS);
    // 14') w[b][m] = sum_n mask[n]·S2[n][m];  msum[b]
    colw_kernel<<<dim3(HWN / 256, BB), 128>>>(pS, mask, pw, pmsum);
    // 15') pmid[b][c] = sum_m w[m]·v2fT[c][m]
    pooledmid_kernel<<<dim3(CC / 8, BB), 256>>>(pw, pv2fT, ppmid);
    // 16') proto = (pmid·ca_wo^T + bo·msum)/(msum+1e-5)
    proto_proj<<<dim3(CC / 8, BB), 256>>>(ppmid, pmsum, ca_wo, ca_bo, pproto);
    // 17) pf projections
    pf_gemv<<<dim3(CC / 8, 3, BB), 256>>>(pproto,
        pf_wq, pf_bq, pf_wk, pf_bk, pf_wv, pf_bv, pqp, pkp, pvp);
    // 18) aw[b] = qp[b]·kp[b]
    aw_kernel<<<BB, 256>>>(pqp, pkp, paw);
    // 19) softmax over batch + weighted sum -> out
    final_kernel<<<1, 512>>>(paw, pvp, (float*)d_out, out_size);
}

// round 15
// speedup vs baseline: 1.2633x; 1.2633x over previous
#include <cuda_runtime.h>
#include <cuda_fp16.h>
#include <math.h>
#include <stdint.h>

#define BB 8
#define CC 512
#define DD 64
#define HWN 2304  // 48*48

// ---------------- scratch (static device globals; no allocation) ----------------
__device__ __half h_qryT[(size_t)BB*HWN*CC];   // [b][n][c]
__device__ __half h_sptT[(size_t)BB*HWN*CC];
__device__ __half h_wq [DD*CC];
__device__ __half h_wk [DD*CC];
__device__ __half h_wv1[CC*CC];
__device__ __half h_wv2[CC*CC];
__device__ __half h_cawq[CC*CC];
__device__ __half h_cawk[CC*CC];
__device__ __half h_cawv[CC*CC];
__device__ __half h_cawo[CC*CC];
__device__ __half h_q  [(size_t)BB*HWN*DD];
__device__ __half h_kt [(size_t)BB*HWN*DD];
__device__ float  g_scores[(size_t)BB*HWN*HWN];
__device__ __half h_S  [(size_t)BB*HWN*HWN];
__device__ __half h_ST [(size_t)BB*HWN*HWN];
__device__ __half h_v1 [(size_t)BB*CC*HWN];    // [b][c][n]
__device__ __half h_v2 [(size_t)BB*CC*HWN];
__device__ __half h_x1 [(size_t)BB*HWN*CC];    // [b][m][c]
__device__ __half h_x2 [(size_t)BB*HWN*CC];
__device__ __half h_q2 [(size_t)BB*HWN*CC];
__device__ __half h_k2 [(size_t)BB*HWN*CC];
__device__ __half h_v2fT[(size_t)BB*CC*HWN];   // [b][c][m]
__device__ float  g_wp  [(size_t)BB*18*HWN];
__device__ float  g_msp [BB*18];
__device__ float  g_w   [BB*HWN];
__device__ float  g_msum[BB];
__device__ float  g_pmid[BB*CC];
__device__ float  g_proto[BB*CC];
__device__ float  g_qp [BB*CC];
__device__ float  g_kp [BB*CC];
__device__ float  g_vp [BB*CC];
__device__ float  g_aw [BB];

// ======================= helpers =======================
__device__ __forceinline__ uint32_t smem_u32(const void* p) {
    uint32_t a;
    asm("{ .reg .u64 t; cvta.to.shared.u64 t, %1; cvt.u32.u64 %0, t; }" : "=r"(a) : "l"(p));
    return a;
}
__device__ __forceinline__ void cpa16(uint32_t dst, const void* src, int sz) {
    asm volatile("cp.async.ca.shared.global [%0], [%1], 16, %2;\n"
                 :: "r"(dst), "l"(src), "r"(sz));
}
#define CPA_COMMIT() asm volatile("cp.async.commit_group;\n" ::: "memory")
#define CPA_WAIT1()  asm volatile("cp.async.wait_group 1;\n" ::: "memory")
#define CPA_WAIT0()  asm volatile("cp.async.wait_group 0;\n" ::: "memory")

// ---------------- fp16 tensor-core GEMM, cp.async + ldmatrix --------------------
// C[i,j] = alpha*sum_k A[i][k]*B[j][k] (+bias)(+res). A,B fp16 row-major k-contig.
// Block tile 128x128, K-tile 32, 2 stages. 8 warps: 2(M) x 4(N), warp tile 64x32.
// Optional second operand set (A2,B2,C2,bias2): used when blockIdx.z >= BB
// (merges two same-shape independent GEMMs into one launch).
#define LDS_ROW 40   // 32 + 8 pad halves = 80B; ldmatrix rows hit disjoint bank quads

template <bool OUT_HALF>
__global__ __launch_bounds__(256, 2)
void hgemm2(int M, int N, int K,
            const __half* __restrict__ A, int lda, long bsA,
            const __half* __restrict__ B, int ldb, long bsB,
            void* __restrict__ Cv, int ldc, long bsC,
            const float* __restrict__ bias, int bias_mode,   // 0 none, 1 per-col(j), 2 per-row(i)
            const float* __restrict__ alpha_ptr, float alpha_const,
            const __half* __restrict__ Rm, int ldr, long bsR,
            const __half* A2, const __half* B2, void* Cv2, const float* bias2)
{
    __shared__ __half As[2][128][LDS_ROW];
    __shared__ __half Bs[2][128][LDS_ROW];

    int bz = blockIdx.z;
    const __half* Ap = A;
    const __half* Bp = B;
    void* Cp = Cv;
    const float* biasp = bias;
    if (A2 != nullptr && bz >= BB) {
        bz -= BB;
        Ap = A2; Bp = B2; Cp = Cv2; biasp = bias2;
    }
    Ap += (long)bz * bsA;
    Bp += (long)bz * bsB;
    if (Rm) Rm += (long)bz * bsR;

    int i0 = blockIdx.y * 128, j0 = blockIdx.x * 128;
    int tid = threadIdx.x;
    int lane = tid & 31, wid = tid >> 5;
    int warp_m = (wid & 1) * 64;
    int warp_n = (wid >> 1) * 32;
    int g = lane >> 2;        // 0..7
    int tg = lane & 3;        // 0..3

    uint32_t sA = smem_u32(&As[0][0][0]);
    uint32_t sB = smem_u32(&Bs[0][0][0]);
    const uint32_t stageBytes = 128 * LDS_ROW * 2;

    // ldmatrix per-lane source rows/cols (within the warp tile)
    int lm_arow = warp_m + (lane & 7) + 8 * ((lane >> 3) & 1);
    int lm_acol = 8 * ((lane >> 4) & 1);
    int lm_brow = warp_n + (lane & 7) + 8 * ((lane >> 4) & 1);
    int lm_bcol = 8 * ((lane >> 3) & 1);

    // per-thread copy tasks: 512 chunks per operand per stage, 2 per thread
    int crow = tid >> 2;          // 0..63 -> two rows: crow, crow+64
    int cch  = tid & 3;           // chunk 0..3 (16B each)

    auto load_tile = [&](int st, int kt) {
        int k0 = kt * 32;
#pragma unroll
        for (int h = 0; h < 2; h++) {
            int row = crow + h * 64;
            uint32_t off = (uint32_t)(row * LDS_ROW + cch * 8) * 2;
            cpa16(sA + st * stageBytes + off,
                  Ap + (long)(i0 + row) * lda + k0 + cch * 8, 16);
            int gj = j0 + row;
            cpa16(sB + st * stageBytes + off,
                  Bp + (long)gj * ldb + k0 + cch * 8, (gj < N) ? 16 : 0);
        }
    };

    float acc[4][4][4];
#pragma unroll
    for (int a = 0; a < 4; a++)
#pragma unroll
        for (int b = 0; b < 4; b++)
#pragma unroll
            for (int c = 0; c < 4; c++) acc[a][b][c] = 0.f;

    int T = K / 32;
    load_tile(0, 0);
    CPA_COMMIT();

    for (int kt = 0; kt < T; kt++) {
        int st = kt & 1;
        if (kt + 1 < T) {
            load_tile(st ^ 1, kt + 1);
            CPA_COMMIT();
            CPA_WAIT1();
        } else {
            CPA_WAIT0();
        }
        __syncthreads();

        uint32_t sAst = sA + st * stageBytes;
        uint32_t sBst = sB + st * stageBytes;
#pragma unroll
        for (int ks = 0; ks < 2; ks++) {
            int kb = ks * 16;
            uint32_t a[4][4];
#pragma unroll
            for (int mt = 0; mt < 4; mt++) {
                uint32_t addr = sAst +
                    (uint32_t)((lm_arow + mt * 16) * LDS_ROW + kb + lm_acol) * 2;
                asm volatile("ldmatrix.sync.aligned.m8n8.x4.shared.b16 {%0,%1,%2,%3}, [%4];"
                    : "=r"(a[mt][0]), "=r"(a[mt][1]), "=r"(a[mt][2]), "=r"(a[mt][3])
                    : "r"(addr));
            }
            uint32_t b[4][2];
#pragma unroll
            for (int np = 0; np < 2; np++) {
                uint32_t addr = sBst +
                    (uint32_t)((lm_brow + np * 16) * LDS_ROW + kb + lm_bcol) * 2;
                asm volatile("ldmatrix.sync.aligned.m8n8.x4.shared.b16 {%0,%1,%2,%3}, [%4];"
                    : "=r"(b[2 * np][0]), "=r"(b[2 * np][1]),
                      "=r"(b[2 * np + 1][0]), "=r"(b[2 * np + 1][1])
                    : "r"(addr));
            }
#pragma unroll
            for (int mt = 0; mt < 4; mt++)
#pragma unroll
                for (int nt = 0; nt < 4; nt++) {
                    asm volatile(
                        "mma.sync.aligned.m16n8k16.row.col.f32.f16.f16.f32 "
                        "{%0,%1,%2,%3}, {%4,%5,%6,%7}, {%8,%9}, {%0,%1,%2,%3};\n"
                        : "+f"(acc[mt][nt][0]), "+f"(acc[mt][nt][1]),
                          "+f"(acc[mt][nt][2]), "+f"(acc[mt][nt][3])
                        : "r"(a[mt][0]), "r"(a[mt][1]), "r"(a[mt][2]), "r"(a[mt][3]),
                          "r"(b[nt][0]), "r"(b[nt][1]));
                }
        }
        __syncthreads();
    }

    float alpha = alpha_const;
    if (alpha_ptr) alpha *= *alpha_ptr;

    float*  Cf = (float*)Cp;
    __half* Ch = (__half*)Cp;
    if (OUT_HALF) Ch += (long)bz * bsC; else Cf += (long)bz * bsC;

#pragma unroll
    for (int mt = 0; mt < 4; mt++) {
#pragma unroll
        for (int nt = 0; nt < 4; nt++) {
            int gj = j0 + warp_n + nt * 8 + tg * 2;
            if (gj >= N) continue;
#pragma unroll
            for (int half_row = 0; half_row < 2; half_row++) {
                int gi = i0 + warp_m + mt * 16 + g + half_row * 8;
                float v0 = alpha * acc[mt][nt][half_row * 2];
                float v1 = alpha * acc[mt][nt][half_row * 2 + 1];
                if (bias_mode == 1) { v0 += biasp[gj]; v1 += biasp[gj + 1]; }
                else if (bias_mode == 2) { float bb = biasp[gi]; v0 += bb; v1 += bb; }
                if (Rm) {
                    uint32_t rr = *(const uint32_t*)(Rm + (long)gi * ldr + gj);
                    __half2 rh = *(__half2*)&rr;
                    v0 += __half2float(rh.x);
                    v1 += __half2float(rh.y);
                }
                if (OUT_HALF) {
                    __half2 o = __floats2half2_rn(v0, v1);
                    *(uint32_t*)(Ch + (long)gi * ldc + gj) = *(uint32_t*)&o;
                } else {
                    *(float2*)(Cf + (long)gi * ldc + gj) = make_float2(v0, v1);
                }
            }
        }
    }
}

// ---------------- all weights fp32 -> fp16 in one launch ----------------
__global__ void w2h_all(const float* s0, const float* s1, const float* s2, const float* s3,
                        const float* s4, const float* s5, const float* s6, const float* s7,
                        __half* d0, __half* d1, __half* d2, __half* d3,
                        __half* d4, __half* d5, __half* d6, __half* d7)
{
    int which = blockIdx.y;
    const float* s; __half* d; int n;
    switch (which) {
        case 0: s = s0; d = d0; n = DD * CC; break;
        case 1: s = s1; d = d1; n = DD * CC; break;
        case 2: s = s2; d = d2; n = CC * CC; break;
        case 3: s = s3; d = d3; n = CC * CC; break;
        case 4: s = s4; d = d4; n = CC * CC; break;
        case 5: s = s5; d = d5; n = CC * CC; break;
        case 6: s = s6; d = d6; n = CC * CC; break;
        default: s = s7; d = d7; n = CC * CC; break;
    }
    int i = blockIdx.x * 1024 + threadIdx.x * 4;
    if (i + 3 < n) {
        float4 f = *(const float4*)(s + i);
        __half2 a = __floats2half2_rn(f.x, f.y);
        __half2 b = __floats2half2_rn(f.z, f.w);
        *(uint2*)(d + i) = make_uint2(*(uint32_t*)&a, *(uint32_t*)&b);
    }
}

// ---------------- transpose+convert: fp32 [C][HWN] -> fp16 [HWN][C], per batch ----
__global__ void tcvt_kernel(const float* __restrict__ src, __half* __restrict__ dst)
{
    __shared__ float tile[32][33];
    int b = blockIdx.z;
    int n0 = blockIdx.x * 32, c0 = blockIdx.y * 32;
    int tx = threadIdx.x, ty = threadIdx.y;  // (32, 8)
    const float* s = src + (long)b * CC * HWN;
    __half* d = dst + (long)b * HWN * CC;
#pragma unroll
    for (int i = 0; i < 4; i++)
        tile[ty + 8 * i][tx] = s[(long)(c0 + ty + 8 * i) * HWN + n0 + tx];
    __syncthreads();
#pragma unroll
    for (int i = 0; i < 4; i++)
        d[(long)(n0 + ty + 8 * i) * CC + c0 + tx] = __float2half(tile[tx][ty + 8 * i]);
}

// ---------------- fp16 transpose [HWN][HWN] per batch ----------------
__global__ void th_kernel(const __half* __restrict__ src, __half* __restrict__ dst)
{
    __shared__ __half tile[32][33];
    int b = blockIdx.z;
    int u0 = blockIdx.y * 32, v0 = blockIdx.x * 32;
    int tx = threadIdx.x, ty = threadIdx.y;  // (32, 8)
    const __half* s = src + (long)b * HWN * HWN;
    __half* d = dst + (long)b * HWN * HWN;
#pragma unroll
    for (int i = 0; i < 4; i++)
        tile[ty + 8 * i][tx] = s[(long)(u0 + ty + 8 * i) * HWN + v0 + tx];
    __syncthreads();
#pragma unroll
    for (int i = 0; i < 4; i++)
        d[(long)(v0 + ty + 8 * i) * HWN + u0 + tx] = tile[tx][ty + 8 * i];
}

// ---------------- row softmax over 2304 cols: fp32 in -> fp16 out ----------------
__global__ void softmax_h(const float* __restrict__ in, __half* __restrict__ out)
{
    long row = blockIdx.x;
    const float* p = in + row * (long)HWN;
    __half* o = out + row * (long)HWN;
    int t = threadIdx.x;
    float v[9];
    float mx = -1e30f;
#pragma unroll
    for (int i = 0; i < 9; i++) { v[i] = p[t + 256 * i]; mx = fmaxf(mx, v[i]); }

    __shared__ float red[256];
    red[t] = mx; __syncthreads();
    for (int s = 128; s > 0; s >>= 1) { if (t < s) red[t] = fmaxf(red[t], red[t + s]); __syncthreads(); }
    mx = red[0]; __syncthreads();

    float sm = 0.f;
#pragma unroll
    for (int i = 0; i < 9; i++) { v[i] = expf(v[i] - mx); sm += v[i]; }
    red[t] = sm; __syncthreads();
    for (int s = 128; s > 0; s >>= 1) { if (t < s) red[t] += red[t + s]; __syncthreads(); }
    float inv = 1.f / red[0];
#pragma unroll
    for (int i = 0; i < 9; i++) o[t + 256 * i] = __float2half(v[i] * inv);
}

// ---- stage 1: wp[b][chunk][m] = sum over 128 n-rows of mask*S2; msp = mask partials ----
__global__ void colw_part(const __half* __restrict__ S2, const float* __restrict__ mask,
                          float* __restrict__ wp, float* __restrict__ msp)
{
    int b = blockIdx.z;
    int chunk = blockIdx.y;               // 18 chunks of 128 rows
    int m0 = blockIdx.x * 256;            // 9 blocks of 256 columns
    int t = threadIdx.x;                  // 128 threads, half2 each
    const __half2* s = (const __half2*)(S2 + (long)b * HWN * HWN + (long)chunk * 128 * HWN + m0) + t;
    const float* mp = mask + (long)b * HWN + chunk * 128;
    float a0 = 0.f, a1 = 0.f, ms = 0.f;
#pragma unroll 4
    for (int n = 0; n < 128; n++) {
        float mk = mp[n];
        float2 f = __half22float2(s[(long)n * (HWN / 2)]);
        a0 += mk * f.x;
        a1 += mk * f.y;
        ms += mk;
    }
    long base = ((long)b * 18 + chunk) * HWN + m0 + 2 * t;
    wp[base] = a0;
    wp[base + 1] = a1;
    if (blockIdx.x == 0 && t == 0) msp[b * 18 + chunk] = ms;
}

// ---- stage 2: w[b][m] = sum_k wp[b][k][m]; msum[b] = sum_k msp[b][k] ----
__global__ void colw_reduce(const float* __restrict__ wp, const float* __restrict__ msp,
                            float* __restrict__ w, float* __restrict__ msum)
{
    int b = blockIdx.y;
    int m = blockIdx.x * 256 + threadIdx.x;
    float acc = 0.f;
#pragma unroll
    for (int k = 0; k < 18; k++) acc += wp[((long)b * 18 + k) * HWN + m];
    w[b * HWN + m] = acc;
    if (blockIdx.x == 0 && threadIdx.x == 0) {
        float s = 0.f;
#pragma unroll
        for (int k = 0; k < 18; k++) s += msp[b * 18 + k];
        msum[b] = s;
    }
}

// ---------------- pmid[b][c] = sum_m w[b][m]*v2fT[b][c][m] ----------------
__global__ void pooledmid_kernel(const float* __restrict__ w, const __half* __restrict__ v2fT,
                                 float* __restrict__ pmid)
{
    int b = blockIdx.y;
    int warp = threadIdx.x >> 5, lane = threadIdx.x & 31;
    int c = blockIdx.x * 8 + warp;
    const float* wb = w + b * HWN;
    const __half* vb = v2fT + (long)b * CC * HWN + (long)c * HWN;
    float acc = 0.f;
    for (int m = lane * 2; m < HWN; m += 64) {
        float2 f = __half22float2(*(const __half2*)(vb + m));
        acc += wb[m] * f.x + wb[m + 1] * f.y;
    }
#pragma unroll
    for (int o = 16; o > 0; o >>= 1) acc += __shfl_xor_sync(0xFFFFFFFFu, acc, o);
    if (lane == 0) pmid[b * CC + c] = acc;
}

// ---------------- proto[b][c2] = (pmid[b]·wo[c2] + bo[c2]*msum[b]) / (msum[b]+1e-5) ----
__global__ void proto_proj(const float* __restrict__ pmid, const float* __restrict__ msum,
                           const float* __restrict__ wo, const float* __restrict__ bo,
                           float* __restrict__ proto)
{
    int b = blockIdx.y;
    int warp = threadIdx.x >> 5, lane = threadIdx.x & 31;
    int c2 = blockIdx.x * 8 + warp;
    const float* pm = pmid + b * CC;
    const float* wr = wo + (long)c2 * CC;
    float acc = 0.f;
    for (int c = lane; c < CC; c += 32) acc += pm[c] * wr[c];
#pragma unroll
    for (int o = 16; o > 0; o >>= 1) acc += __shfl_xor_sync(0xFFFFFFFFu, acc, o);
    if (lane == 0) {
        float S = msum[b] + 1e-5f;
        proto[b * CC + c2] = (acc + bo[c2] * msum[b]) / S;
    }
}

// ---------------- pf projections ----------------
__global__ void pf_gemv(const float* __restrict__ proto,
                        const float* __restrict__ wq, const float* __restrict__ bq,
                        const float* __restrict__ wk, const float* __restrict__ bk,
                        const float* __restrict__ wv, const float* __restrict__ bv,
                        float* __restrict__ qp, float* __restrict__ kp, float* __restrict__ vp)
{
    int b = blockIdx.z, which = blockIdx.y;
    const float* W    = (which == 0) ? wq : (which == 1) ? wk : wv;
    const float* bias = (which == 0) ? bq : (which == 1) ? bk : bv;
    float* out        = (which == 0) ? qp : (which == 1) ? kp : vp;
    int warp = threadIdx.x >> 5, lane = threadIdx.x & 31;
    int c2 = blockIdx.x * 8 + warp;
    const float* pr = proto + b * CC;
    const float* wr = W + (long)c2 * CC;
    float acc = 0.f;
    for (int c = lane; c < CC; c += 32) acc += pr[c] * wr[c];
#pragma unroll
    for (int o = 16; o > 0; o >>= 1) acc += __shfl_xor_sync(0xFFFFFFFFu, acc, o);
    if (lane == 0) out[b * CC + c2] = acc + bias[c2];
}

__global__ void aw_kernel(const float* __restrict__ qp, const float* __restrict__ kp,
                          float* __restrict__ aw)
{
    int b = blockIdx.x, t = threadIdx.x;
    float acc = 0.f;
    for (int c = t; c < CC; c += 256) acc += qp[b * CC + c] * kp[b * CC + c];
    __shared__ float red[256];
    red[t] = acc; __syncthreads();
    for (int s = 128; s > 0; s >>= 1) { if (t < s) red[t] += red[t + s]; __syncthreads(); }
    if (t == 0) aw[b] = red[0];
}

__global__ void final_kernel(const float* __restrict__ aw, const float* __restrict__ vp,
                             float* __restrict__ out, int out_size)
{
    int c = threadIdx.x;
    float a[BB];
    float mx = -1e30f;
#pragma unroll
    for (int b = 0; b < BB; b++) { a[b] = aw[b]; mx = fmaxf(mx, a[b]); }
    float s = 0.f;
#pragma unroll
    for (int b = 0; b < BB; b++) { a[b] = expf(a[b] - mx); s += a[b]; }
    float inv = 1.f / s;
    float f = 0.f;
#pragma unroll
    for (int b = 0; b < BB; b++) f += a[b] * inv * vp[b * CC + c];
    if (c < out_size) out[c] = f;
}

// ---------------------------------------------------------------------------------------------
extern "C" void kernel_launch(void* const* d_in, const int* in_sizes, int n_in,
                              void* d_out, int out_size)
{
    const float* qry   = (const float*)d_in[0];
    const float* spt   = (const float*)d_in[1];
    const float* mask  = (const float*)d_in[2];
    const float* w_wq  = (const float*)d_in[3];
    const float* b_wq  = (const float*)d_in[4];
    const float* w_wk  = (const float*)d_in[5];
    const float* b_wk  = (const float*)d_in[6];
    const float* w_wv1 = (const float*)d_in[7];
    const float* b_wv1 = (const float*)d_in[8];
    const float* w_wv2 = (const float*)d_in[9];
    const float* b_wv2 = (const float*)d_in[10];
    const float* gamma1 = (const float*)d_in[11];
    const float* gamma2 = (const float*)d_in[12];
    const float* ca_wq = (const float*)d_in[13];
    const float* ca_bq = (const float*)d_in[14];
    const float* ca_wk = (const float*)d_in[15];
    const float* ca_bk = (const float*)d_in[16];
    const float* ca_wv = (const float*)d_in[17];
    const float* ca_bv = (const float*)d_in[18];
    const float* ca_wo = (const float*)d_in[19];
    const float* ca_bo = (const float*)d_in[20];
    const float* pf_wq = (const float*)d_in[21];
    const float* pf_bq = (const float*)d_in[22];
    const float* pf_wk = (const float*)d_in[23];
    const float* pf_bk = (const float*)d_in[24];
    const float* pf_wv = (const float*)d_in[25];
    const float* pf_bv = (const float*)d_in[26];

    __half *pqT, *psT, *pwq, *pwk, *pwv1, *pwv2, *pcq, *pck, *pcv, *pco;
    __half *pq, *pkt, *pS, *pST, *pv1, *pv2, *px1, *px2, *pq2, *pk2, *pv2fT;
    float *pscores, *pwp, *pmsp, *pw, *pmsum, *ppmid, *pproto, *pqp, *pkp, *pvp, *paw;
    cudaGetSymbolAddress((void**)&pqT, h_qryT);
    cudaGetSymbolAddress((void**)&psT, h_sptT);
    cudaGetSymbolAddress((void**)&pwq, h_wq);
    cudaGetSymbolAddress((void**)&pwk, h_wk);
    cudaGetSymbolAddress((void**)&pwv1, h_wv1);
    cudaGetSymbolAddress((void**)&pwv2, h_wv2);
    cudaGetSymbolAddress((void**)&pcq, h_cawq);
    cudaGetSymbolAddress((void**)&pck, h_cawk);
    cudaGetSymbolAddress((void**)&pcv, h_cawv);
    cudaGetSymbolAddress((void**)&pco, h_cawo);
    cudaGetSymbolAddress((void**)&pq, h_q);
    cudaGetSymbolAddress((void**)&pkt, h_kt);
    cudaGetSymbolAddress((void**)&pscores, g_scores);
    cudaGetSymbolAddress((void**)&pS, h_S);
    cudaGetSymbolAddress((void**)&pST, h_ST);
    cudaGetSymbolAddress((void**)&pv1, h_v1);
    cudaGetSymbolAddress((void**)&pv2, h_v2);
    cudaGetSymbolAddress((void**)&px1, h_x1);
    cudaGetSymbolAddress((void**)&px2, h_x2);
    cudaGetSymbolAddress((void**)&pq2, h_q2);
    cudaGetSymbolAddress((void**)&pk2, h_k2);
    cudaGetSymbolAddress((void**)&pv2fT, h_v2fT);
    cudaGetSymbolAddress((void**)&pwp, g_wp);
    cudaGetSymbolAddress((void**)&pmsp, g_msp);
    cudaGetSymbolAddress((void**)&pw, g_w);
    cudaGetSymbolAddress((void**)&pmsum, g_msum);
    cudaGetSymbolAddress((void**)&ppmid, g_pmid);
    cudaGetSymbolAddress((void**)&pproto, g_proto);
    cudaGetSymbolAddress((void**)&pqp, g_qp);
    cudaGetSymbolAddress((void**)&pkp, g_kp);
    cudaGetSymbolAddress((void**)&pvp, g_vp);
    cudaGetSymbolAddress((void**)&paw, g_aw);

    const long NC   = (long)HWN * CC;     // 2304*512
    const long ND   = (long)HWN * DD;
    const long NN   = (long)HWN * HWN;
    dim3 blk(256);
    const float inv_sqrt_c = 0.044194173824159216f;

    // 0a) all weights -> fp16, one launch
    w2h_all<<<dim3((CC * CC) / 1024, 8), 256>>>(
        w_wq, w_wk, w_wv1, w_wv2, ca_wq, ca_wk, ca_wv, ca_wo,
        pwq, pwk, pwv1, pwv2, pcq, pck, pcv, pco);
    // 0b) qry/spt -> fp16 transposed [n][c]
    tcvt_kernel<<<dim3(HWN / 32, CC / 32, BB), dim3(32, 8)>>>(qry, pqT);
    tcvt_kernel<<<dim3(HWN / 32, CC / 32, BB), dim3(32, 8)>>>(spt, psT);

    // 1+2) q/kt merged: q[n][d] = qryT·wq^T + b ; kt[n][d] = sptT·wk^T + b
    hgemm2<true><<<dim3(1, 18, 2 * BB), blk>>>(HWN, DD, CC,
        pqT, CC, NC,  pwq, CC, 0,  pq, DD, ND,  b_wq, 1, nullptr, 1.f, nullptr, 0, 0,
        psT, pwk, pkt, b_wk);
    // 3) scores1[n][m] = q·kt^T   (M=N=2304,K=64)
    hgemm2<false><<<dim3(18, 18, BB), blk>>>(HWN, HWN, DD,
        pq, DD, ND,  pkt, DD, ND,  pscores, HWN, NN,  nullptr, 0, nullptr, 1.f, nullptr, 0, 0,
        nullptr, nullptr, nullptr, nullptr);
    // 4) softmax -> S fp16 ; transpose -> ST
    softmax_h<<<BB * HWN, 256>>>(pscores, pS);
    th_kernel<<<dim3(HWN / 32, HWN / 32, BB), dim3(32, 8)>>>(pS, pST);
    // 5+6) v1/v2 merged: v1[c][n] = wv1·qry + b ; v2[c][n] = wv2·spt + b (bias per-row c)
    hgemm2<true><<<dim3(18, 4, 2 * BB), blk>>>(CC, HWN, CC,
        pwv1, CC, 0,  pqT, CC, NC,  pv1, HWN, (long)CC * HWN,  b_wv1, 2, nullptr, 1.f, nullptr, 0, 0,
        pwv2, psT, pv2, b_wv2);
    // 7) x1[m][c] = gamma1·sum_n S[m][n]·v1[c][n] + qryT[m][c]  (M=2304,N=512,K=2304)
    hgemm2<true><<<dim3(4, 18, BB), blk>>>(HWN, CC, HWN,
        pS, HWN, NN,  pv1, HWN, (long)CC * HWN,  px1, CC, NC,
        nullptr, 0, gamma1, 1.f, pqT, CC, NC,
        nullptr, nullptr, nullptr, nullptr);
    // 8) x2[m][c] = gamma2·sum_n ST[m][n]·v2[c][n] + sptT[m][c]
    hgemm2<true><<<dim3(4, 18, BB), blk>>>(HWN, CC, HWN,
        pST, HWN, NN,  pv2, HWN, (long)CC * HWN,  px2, CC, NC,
        nullptr, 0, gamma2, 1.f, psT, CC, NC,
        nullptr, nullptr, nullptr, nullptr);
    // 9+10) q2/k2 merged: q2 = x1·ca_wq^T + b ; k2 = x2·ca_wk^T + b  (M=2304,N=512,K=512)
    hgemm2<true><<<dim3(4, 18, 2 * BB), blk>>>(HWN, CC, CC,
        px1, CC, NC,  pcq, CC, 0,  pq2, CC, NC,  ca_bq, 1, nullptr, 1.f, nullptr, 0, 0,
        px2, pck, pk2, ca_bk);
    // 11) v2fT[c][m] = ca_wv·x2^T + b  (M=512,N=2304,K=512), bias per-row c
    hgemm2<true><<<dim3(18, 4, BB), blk>>>(CC, HWN, CC,
        pcv, CC, 0,  px2, CC, NC,  pv2fT, HWN, (long)CC * HWN,  ca_bv, 2, nullptr, 1.f, nullptr, 0, 0,
        nullptr, nullptr, nullptr, nullptr);
    // 12) scores2[n][m] = q2·k2^T /sqrt(C)  (M=N=2304,K=512)
    hgemm2<false><<<dim3(18, 18, BB), blk>>>(HWN, HWN, CC,
        pq2, CC, NC,  pk2, CC, NC,  pscores, HWN, NN,  nullptr, 0, nullptr, inv_sqrt_c, nullptr, 0, 0,
        nullptr, nullptr, nullptr, nullptr);
    // 13) softmax -> S2 fp16 (reuse h_S)
    softmax_h<<<BB * HWN, 256>>>(pscores, pS);
    // 14') two-stage column reduction: w[b][m] = sum_n mask[n]·S2[n][m]
    colw_part<<<dim3(HWN / 256, 18, BB), 128>>>(pS, mask, pwp, pmsp);
    colw_reduce<<<dim3(HWN / 256, BB), 256>>>(pwp, pmsp, pw, pmsum);
    // 15') pmid[b][c] = sum_m w[m]·v2fT[c][m]
    pooledmid_kernel<<<dim3(CC / 8, BB), 256>>>(pw, pv2fT, ppmid);
    // 16') proto = (pmid·ca_wo^T + bo·msum)/(msum+1e-5)
    proto_proj<<<dim3(CC / 8, BB), 256>>>(ppmid, pmsum, ca_wo, ca_bo, pproto);
    // 17) pf projections
    pf_gemv<<<dim3(CC / 8, 3, BB), 256>>>(pproto,
        pf_wq, pf_bq, pf_wk, pf_bk, pf_wv, pf_bv, pqp, pkp, pvp);
    // 18) aw[b] = qp[b]·kp[b]
    aw_kernel<<<BB, 256>>>(pqp, pkp, paw);
    // 19) softmax over batch + weighted sum -> out
    final_kernel<<<1, 512>>>(paw, pvp, (float*)d_out, out_size);
}

// round 17
// speedup vs baseline: 1.2843x; 1.0166x over previous
#include <cuda_runtime.h>
#include <cuda_fp16.h>
#include <math.h>
#include <stdint.h>

#define BB 8
#define CC 512
#define DD 64
#define HWN 2304  // 48*48

// ---------------- scratch (static device globals; no allocation) ----------------
__device__ __half h_qryT[(size_t)BB*HWN*CC];   // [b][n][c]
__device__ __half h_sptT[(size_t)BB*HWN*CC];
__device__ __half h_wq [DD*CC];
__device__ __half h_wk [DD*CC];
__device__ __half h_wv1[CC*CC];
__device__ __half h_wv2[CC*CC];
__device__ __half h_cawq[CC*CC];
__device__ __half h_cawk[CC*CC];
__device__ __half h_cawv[CC*CC];
__device__ __half h_cawo[CC*CC];
__device__ __half h_q  [(size_t)BB*HWN*DD];
__device__ __half h_kt [(size_t)BB*HWN*DD];
__device__ float  g_scores[(size_t)BB*HWN*HWN];
__device__ __half h_S  [(size_t)BB*HWN*HWN];
__device__ __half h_ST [(size_t)BB*HWN*HWN];
__device__ __half h_v1 [(size_t)BB*CC*HWN];    // [b][c][n]
__device__ __half h_v2 [(size_t)BB*CC*HWN];
__device__ __half h_x1 [(size_t)BB*HWN*CC];    // [b][m][c]
__device__ __half h_x2 [(size_t)BB*HWN*CC];
__device__ __half h_q2 [(size_t)BB*HWN*CC];
__device__ __half h_k2 [(size_t)BB*HWN*CC];
__device__ __half h_v2fT[(size_t)BB*CC*HWN];   // [b][c][m]
__device__ float  g_wp  [(size_t)BB*18*HWN];
__device__ float  g_msp [BB*18];
__device__ float  g_w   [BB*HWN];
__device__ float  g_msum[BB];
__device__ float  g_pmid[BB*CC];
__device__ float  g_proto[BB*CC];
__device__ float  g_qp [BB*CC];
__device__ float  g_kp [BB*CC];
__device__ float  g_vp [BB*CC];
__device__ float  g_aw [BB];

// ======================= helpers =======================
__device__ __forceinline__ uint32_t smem_u32(const void* p) {
    uint32_t a;
    asm("{ .reg .u64 t; cvta.to.shared.u64 t, %1; cvt.u32.u64 %0, t; }" : "=r"(a) : "l"(p));
    return a;
}
__device__ __forceinline__ void cpa16(uint32_t dst, const void* src, int sz) {
    asm volatile("cp.async.ca.shared.global [%0], [%1], 16, %2;\n"
                 :: "r"(dst), "l"(src), "r"(sz));
}
#define CPA_COMMIT() asm volatile("cp.async.commit_group;\n" ::: "memory")
#define CPA_WAIT2()  asm volatile("cp.async.wait_group 2;\n" ::: "memory")
#define CPA_WAIT1()  asm volatile("cp.async.wait_group 1;\n" ::: "memory")
#define CPA_WAIT0()  asm volatile("cp.async.wait_group 0;\n" ::: "memory")

// ---------------- fp16 tensor-core GEMM, 3-stage cp.async + ldmatrix ------------
// C[i,j] = alpha*sum_k A[i][k]*B[j][k] (+bias)(+res). A,B fp16 row-major k-contig.
// Block tile 128x128, K-tile 32, 3 stages. 8 warps: 2(M) x 4(N), warp tile 64x32.
// Optional second operand set (A2,B2,C2,bias2,Rm2,alpha2): used when blockIdx.z >= BB.
#define LDS_ROW 40                          // 32 + 8 pad halves = 80B
#define STAGE_BYTES (128 * LDS_ROW * 2)     // 10240 per operand per stage
#define SMEM_HG (2 * 3 * STAGE_BYTES)       // 61440 bytes dynamic

template <bool OUT_HALF>
__global__ __launch_bounds__(256, 2)
void hgemm2(int M, int N, int K,
            const __half* __restrict__ A, int lda, long bsA,
            const __half* __restrict__ B, int ldb, long bsB,
            void* __restrict__ Cv, int ldc, long bsC,
            const float* __restrict__ bias, int bias_mode,   // 0 none, 1 per-col(j), 2 per-row(i)
            const float* __restrict__ alpha_ptr, float alpha_const,
            const __half* __restrict__ Rm, int ldr, long bsR,
            const __half* A2, const __half* B2, void* Cv2, const float* bias2,
            const __half* Rm2, const float* alpha_ptr2)
{
    extern __shared__ char smem[];

    int bz = blockIdx.z;
    const __half* Ap = A;
    const __half* Bp = B;
    void* Cp = Cv;
    const float* biasp = bias;
    const __half* Rp = Rm;
    const float* alphap = alpha_ptr;
    if (A2 != nullptr && bz >= BB) {
        bz -= BB;
        Ap = A2; Bp = B2; Cp = Cv2; biasp = bias2; Rp = Rm2; alphap = alpha_ptr2;
    }
    Ap += (long)bz * bsA;
    Bp += (long)bz * bsB;
    if (Rp) Rp += (long)bz * bsR;

    int i0 = blockIdx.y * 128, j0 = blockIdx.x * 128;
    int tid = threadIdx.x;
    int lane = tid & 31, wid = tid >> 5;
    int warp_m = (wid & 1) * 64;
    int warp_n = (wid >> 1) * 32;
    int g = lane >> 2;        // 0..7
    int tg = lane & 3;        // 0..3

    uint32_t sA = smem_u32(smem);
    uint32_t sB = sA + 3 * STAGE_BYTES;

    // ldmatrix per-lane source rows/cols (within the warp tile)
    int lm_arow = warp_m + (lane & 7) + 8 * ((lane >> 3) & 1);
    int lm_acol = 8 * ((lane >> 4) & 1);
    int lm_brow = warp_n + (lane & 7) + 8 * ((lane >> 4) & 1);
    int lm_bcol = 8 * ((lane >> 3) & 1);

    // per-thread copy tasks: 512 chunks per operand per stage, 2 per thread
    int crow = tid >> 2;          // 0..63 -> two rows: crow, crow+64
    int cch  = tid & 3;           // chunk 0..3 (16B each)

    auto load_tile = [&](int st, int kt) {
        int k0 = kt * 32;
#pragma unroll
        for (int h = 0; h < 2; h++) {
            int row = crow + h * 64;
            uint32_t off = (uint32_t)(row * LDS_ROW + cch * 8) * 2;
            cpa16(sA + st * STAGE_BYTES + off,
                  Ap + (long)(i0 + row) * lda + k0 + cch * 8, 16);
            int gj = j0 + row;
            cpa16(sB + st * STAGE_BYTES + off,
                  Bp + (long)gj * ldb + k0 + cch * 8, (gj < N) ? 16 : 0);
        }
    };

    float acc[4][4][4];
#pragma unroll
    for (int a = 0; a < 4; a++)
#pragma unroll
        for (int b = 0; b < 4; b++)
#pragma unroll
            for (int c = 0; c < 4; c++) acc[a][b][c] = 0.f;

    int T = K / 32;
    load_tile(0, 0);
    CPA_COMMIT();
    if (T > 1) { load_tile(1, 1); CPA_COMMIT(); }

    for (int kt = 0; kt < T; kt++) {
        int st = kt % 3;
        if (kt + 2 < T) {
            load_tile((kt + 2) % 3, kt + 2);
            CPA_COMMIT();
            CPA_WAIT2();
        } else if (kt + 1 < T) {
            CPA_WAIT1();
        } else {
            CPA_WAIT0();
        }
        __syncthreads();

        uint32_t sAst = sA + st * STAGE_BYTES;
        uint32_t sBst = sB + st * STAGE_BYTES;
#pragma unroll
        for (int ks = 0; ks < 2; ks++) {
            int kb = ks * 16;
            uint32_t a[4][4];
#pragma unroll
            for (int mt = 0; mt < 4; mt++) {
                uint32_t addr = sAst +
                    (uint32_t)((lm_arow + mt * 16) * LDS_ROW + kb + lm_acol) * 2;
                asm volatile("ldmatrix.sync.aligned.m8n8.x4.shared.b16 {%0,%1,%2,%3}, [%4];"
                    : "=r"(a[mt][0]), "=r"(a[mt][1]), "=r"(a[mt][2]), "=r"(a[mt][3])
                    : "r"(addr));
            }
            uint32_t b[4][2];
#pragma unroll
            for (int np = 0; np < 2; np++) {
                uint32_t addr = sBst +
                    (uint32_t)((lm_brow + np * 16) * LDS_ROW + kb + lm_bcol) * 2;
                asm volatile("ldmatrix.sync.aligned.m8n8.x4.shared.b16 {%0,%1,%2,%3}, [%4];"
                    : "=r"(b[2 * np][0]), "=r"(b[2 * np][1]),
                      "=r"(b[2 * np + 1][0]), "=r"(b[2 * np + 1][1])
                    : "r"(addr));
            }
#pragma unroll
            for (int mt = 0; mt < 4; mt++)
#pragma unroll
                for (int nt = 0; nt < 4; nt++) {
                    asm volatile(
                        "mma.sync.aligned.m16n8k16.row.col.f32.f16.f16.f32 "
                        "{%0,%1,%2,%3}, {%4,%5,%6,%7}, {%8,%9}, {%0,%1,%2,%3};\n"
                        : "+f"(acc[mt][nt][0]), "+f"(acc[mt][nt][1]),
                          "+f"(acc[mt][nt][2]), "+f"(acc[mt][nt][3])
                        : "r"(a[mt][0]), "r"(a[mt][1]), "r"(a[mt][2]), "r"(a[mt][3]),
                          "r"(b[nt][0]), "r"(b[nt][1]));
                }
        }
        __syncthreads();
    }

    float alpha = alpha_const;
    if (alphap) alpha *= *alphap;

    float*  Cf = (float*)Cp;
    __half* Ch = (__half*)Cp;
    if (OUT_HALF) Ch += (long)bz * bsC; else Cf += (long)bz * bsC;

#pragma unroll
    for (int mt = 0; mt < 4; mt++) {
#pragma unroll
        for (int nt = 0; nt < 4; nt++) {
            int gj = j0 + warp_n + nt * 8 + tg * 2;
            if (gj >= N) continue;
#pragma unroll
            for (int half_row = 0; half_row < 2; half_row++) {
                int gi = i0 + warp_m + mt * 16 + g + half_row * 8;
                float v0 = alpha * acc[mt][nt][half_row * 2];
                float v1 = alpha * acc[mt][nt][half_row * 2 + 1];
                if (bias_mode == 1) { v0 += biasp[gj]; v1 += biasp[gj + 1]; }
                else if (bias_mode == 2) { float bb = biasp[gi]; v0 += bb; v1 += bb; }
                if (Rp) {
                    uint32_t rr = *(const uint32_t*)(Rp + (long)gi * ldr + gj);
                    __half2 rh = *(__half2*)&rr;
                    v0 += __half2float(rh.x);
                    v1 += __half2float(rh.y);
                }
                if (OUT_HALF) {
                    __half2 o = __floats2half2_rn(v0, v1);
                    *(uint32_t*)(Ch + (long)gi * ldc + gj) = *(uint32_t*)&o;
                } else {
                    *(float2*)(Cf + (long)gi * ldc + gj) = make_float2(v0, v1);
                }
            }
        }
    }
}

// ---------------- all weights fp32 -> fp16 in one launch ----------------
__global__ void w2h_all(const float* s0, const float* s1, const float* s2, const float* s3,
                        const float* s4, const float* s5, const float* s6, const float* s7,
                        __half* d0, __half* d1, __half* d2, __half* d3,
                        __half* d4, __half* d5, __half* d6, __half* d7)
{
    int which = blockIdx.y;
    const float* s; __half* d; int n;
    switch (which) {
        case 0: s = s0; d = d0; n = DD * CC; break;
        case 1: s = s1; d = d1; n = DD * CC; break;
        case 2: s = s2; d = d2; n = CC * CC; break;
        case 3: s = s3; d = d3; n = CC * CC; break;
        case 4: s = s4; d = d4; n = CC * CC; break;
        case 5: s = s5; d = d5; n = CC * CC; break;
        case 6: s = s6; d = d6; n = CC * CC; break;
        default: s = s7; d = d7; n = CC * CC; break;
    }
    int i = blockIdx.x * 1024 + threadIdx.x * 4;
    if (i + 3 < n) {
        float4 f = *(const float4*)(s + i);
        __half2 a = __floats2half2_rn(f.x, f.y);
        __half2 b = __floats2half2_rn(f.z, f.w);
        *(uint2*)(d + i) = make_uint2(*(uint32_t*)&a, *(uint32_t*)&b);
    }
}

// ---------------- transpose+convert: fp32 [C][HWN] -> fp16 [HWN][C], per batch ----
__global__ void tcvt_kernel(const float* __restrict__ src, __half* __restrict__ dst)
{
    __shared__ float tile[32][33];
    int b = blockIdx.z;
    int n0 = blockIdx.x * 32, c0 = blockIdx.y * 32;
    int tx = threadIdx.x, ty = threadIdx.y;  // (32, 8)
    const float* s = src + (long)b * CC * HWN;
    __half* d = dst + (long)b * HWN * CC;
#pragma unroll
    for (int i = 0; i < 4; i++)
        tile[ty + 8 * i][tx] = s[(long)(c0 + ty + 8 * i) * HWN + n0 + tx];
    __syncthreads();
#pragma unroll
    for (int i = 0; i < 4; i++)
        d[(long)(n0 + ty + 8 * i) * CC + c0 + tx] = __float2half(tile[tx][ty + 8 * i]);
}

// ---------------- fp16 transpose [HWN][HWN] per batch ----------------
__global__ void th_kernel(const __half* __restrict__ src, __half* __restrict__ dst)
{
    __shared__ __half tile[32][33];
    int b = blockIdx.z;
    int u0 = blockIdx.y * 32, v0 = blockIdx.x * 32;
    int tx = threadIdx.x, ty = threadIdx.y;  // (32, 8)
    const __half* s = src + (long)b * HWN * HWN;
    __half* d = dst + (long)b * HWN * HWN;
#pragma unroll
    for (int i = 0; i < 4; i++)
        tile[ty + 8 * i][tx] = s[(long)(u0 + ty + 8 * i) * HWN + v0 + tx];
    __syncthreads();
#pragma unroll
    for (int i = 0; i < 4; i++)
        d[(long)(v0 + ty + 8 * i) * HWN + u0 + tx] = tile[tx][ty + 8 * i];
}

// ---------------- row softmax over 2304 cols: fp32 in -> fp16 out ----------------
__global__ void softmax_h(const float* __restrict__ in, __half* __restrict__ out)
{
    long row = blockIdx.x;
    const float* p = in + row * (long)HWN;
    __half* o = out + row * (long)HWN;
    int t = threadIdx.x;
    float v[9];
    float mx = -1e30f;
#pragma unroll
    for (int i = 0; i < 9; i++) { v[i] = p[t + 256 * i]; mx = fmaxf(mx, v[i]); }

    __shared__ float red[256];
    red[t] = mx; __syncthreads();
    for (int s = 128; s > 0; s >>= 1) { if (t < s) red[t] = fmaxf(red[t], red[t + s]); __syncthreads(); }
    mx = red[0]; __syncthreads();

    float sm = 0.f;
#pragma unroll
    for (int i = 0; i < 9; i++) { v[i] = expf(v[i] - mx); sm += v[i]; }
    red[t] = sm; __syncthreads();
    for (int s = 128; s > 0; s >>= 1) { if (t < s) red[t] += red[t + s]; __syncthreads(); }
    float inv = 1.f / red[0];
#pragma unroll
    for (int i = 0; i < 9; i++) o[t + 256 * i] = __float2half(v[i] * inv);
}

// ---- stage 1: wp[b][chunk][m] = sum over 128 n-rows of mask*S2; msp = mask partials ----
__global__ void colw_part(const __half* __restrict__ S2, const float* __restrict__ mask,
                          float* __restrict__ wp, float* __restrict__ msp)
{
    int b = blockIdx.z;
    int chunk = blockIdx.y;               // 18 chunks of 128 rows
    int m0 = blockIdx.x * 256;            // 9 blocks of 256 columns
    int t = threadIdx.x;                  // 128 threads, half2 each
    const __half2* s = (const __half2*)(S2 + (long)b * HWN * HWN + (long)chunk * 128 * HWN + m0) + t;
    const float* mp = mask + (long)b * HWN + chunk * 128;
    float a0 = 0.f, a1 = 0.f, ms = 0.f;
#pragma unroll 4
    for (int n = 0; n < 128; n++) {
        float mk = mp[n];
        float2 f = __half22float2(s[(long)n * (HWN / 2)]);
        a0 += mk * f.x;
        a1 += mk * f.y;
        ms += mk;
    }
    long base = ((long)b * 18 + chunk) * HWN + m0 + 2 * t;
    wp[base] = a0;
    wp[base + 1] = a1;
    if (blockIdx.x == 0 && t == 0) msp[b * 18 + chunk] = ms;
}

// ---- stage 2: w[b][m] = sum_k wp[b][k][m]; msum[b] = sum_k msp[b][k] ----
__global__ void colw_reduce(const float* __restrict__ wp, const float* __restrict__ msp,
                            float* __restrict__ w, float* __restrict__ msum)
{
    int b = blockIdx.y;
    int m = blockIdx.x * 256 + threadIdx.x;
    float acc = 0.f;
#pragma unroll
    for (int k = 0; k < 18; k++) acc += wp[((long)b * 18 + k) * HWN + m];
    w[b * HWN + m] = acc;
    if (blockIdx.x == 0 && threadIdx.x == 0) {
        float s = 0.f;
#pragma unroll
        for (int k = 0; k < 18; k++) s += msp[b * 18 + k];
        msum[b] = s;
    }
}

// ---------------- pmid[b][c] = sum_m w[b][m]*v2fT[b][c][m] ----------------
__global__ void pooledmid_kernel(const float* __restrict__ w, const __half* __restrict__ v2fT,
                                 float* __restrict__ pmid)
{
    int b = blockIdx.y;
    int warp = threadIdx.x >> 5, lane = threadIdx.x & 31;
    int c = blockIdx.x * 8 + warp;
    const float* wb = w + b * HWN;
    const __half* vb = v2fT + (long)b * CC * HWN + (long)c * HWN;
    float acc = 0.f;
    for (int m = lane * 2; m < HWN; m += 64) {
        float2 f = __half22float2(*(const __half2*)(vb + m));
        acc += wb[m] * f.x + wb[m + 1] * f.y;
    }
#pragma unroll
    for (int o = 16; o > 0; o >>= 1) acc += __shfl_xor_sync(0xFFFFFFFFu, acc, o);
    if (lane == 0) pmid[b * CC + c] = acc;
}

// ---------------- proto[b][c2] = (pmid[b]·wo[c2] + bo[c2]*msum[b]) / (msum[b]+1e-5) ----
__global__ void proto_proj(const float* __restrict__ pmid, const float* __restrict__ msum,
                           const float* __restrict__ wo, const float* __restrict__ bo,
                           float* __restrict__ proto)
{
    int b = blockIdx.y;
    int warp = threadIdx.x >> 5, lane = threadIdx.x & 31;
    int c2 = blockIdx.x * 8 + warp;
    const float* pm = pmid + b * CC;
    const float* wr = wo + (long)c2 * CC;
    float acc = 0.f;
    for (int c = lane; c < CC; c += 32) acc += pm[c] * wr[c];
#pragma unroll
    for (int o = 16; o > 0; o >>= 1) acc += __shfl_xor_sync(0xFFFFFFFFu, acc, o);
    if (lane == 0) {
        float S = msum[b] + 1e-5f;
        proto[b * CC + c2] = (acc + bo[c2] * msum[b]) / S;
    }
}

// ---------------- pf projections ----------------
__global__ void pf_gemv(const float* __restrict__ proto,
                        const float* __restrict__ wq, const float* __restrict__ bq,
                        const float* __restrict__ wk, const float* __restrict__ bk,
                        const float* __restrict__ wv, const float* __restrict__ bv,
                        float* __restrict__ qp, float* __restrict__ kp, float* __restrict__ vp)
{
    int b = blockIdx.z, which = blockIdx.y;
    const float* W    = (which == 0) ? wq : (which == 1) ? wk : wv;
    const float* bias = (which == 0) ? bq : (which == 1) ? bk : bv;
    float* out        = (which == 0) ? qp : (which == 1) ? kp : vp;
    int warp = threadIdx.x >> 5, lane = threadIdx.x & 31;
    int c2 = blockIdx.x * 8 + warp;
    const float* pr = proto + b * CC;
    const float* wr = W + (long)c2 * CC;
    float acc = 0.f;
    for (int c = lane; c < CC; c += 32) acc += pr[c] * wr[c];
#pragma unroll
    for (int o = 16; o > 0; o >>= 1) acc += __shfl_xor_sync(0xFFFFFFFFu, acc, o);
    if (lane == 0) out[b * CC + c2] = acc + bias[c2];
}

__global__ void aw_kernel(const float* __restrict__ qp, const float* __restrict__ kp,
                          float* __restrict__ aw)
{
    int b = blockIdx.x, t = threadIdx.x;
    float acc = 0.f;
    for (int c = t; c < CC; c += 256) acc += qp[b * CC + c] * kp[b * CC + c];
    __shared__ float red[256];
    red[t] = acc; __syncthreads();
    for (int s = 128; s > 0; s >>= 1) { if (t < s) red[t] += red[t + s]; __syncthreads(); }
    if (t == 0) aw[b] = red[0];
}

__global__ void final_kernel(const float* __restrict__ aw, const float* __restrict__ vp,
                             float* __restrict__ out, int out_size)
{
    int c = threadIdx.x;
    float a[BB];
    float mx = -1e30f;
#pragma unroll
    for (int b = 0; b < BB; b++) { a[b] = aw[b]; mx = fmaxf(mx, a[b]); }
    float s = 0.f;
#pragma unroll
    for (int b = 0; b < BB; b++) { a[b] = expf(a[b] - mx); s += a[b]; }
    float inv = 1.f / s;
    float f = 0.f;
#pragma unroll
    for (int b = 0; b < BB; b++) f += a[b] * inv * vp[b * CC + c];
    if (c < out_size) out[c] = f;
}

// ---------------------------------------------------------------------------------------------
extern "C" void kernel_launch(void* const* d_in, const int* in_sizes, int n_in,
                              void* d_out, int out_size)
{
    const float* qry   = (const float*)d_in[0];
    const float* spt   = (const float*)d_in[1];
    const float* mask  = (const float*)d_in[2];
    const float* w_wq  = (const float*)d_in[3];
    const float* b_wq  = (const float*)d_in[4];
    const float* w_wk  = (const float*)d_in[5];
    const float* b_wk  = (const float*)d_in[6];
    const float* w_wv1 = (const float*)d_in[7];
    const float* b_wv1 = (const float*)d_in[8];
    const float* w_wv2 = (const float*)d_in[9];
    const float* b_wv2 = (const float*)d_in[10];
    const float* gamma1 = (const float*)d_in[11];
    const float* gamma2 = (const float*)d_in[12];
    const float* ca_wq = (const float*)d_in[13];
    const float* ca_bq = (const float*)d_in[14];
    const float* ca_wk = (const float*)d_in[15];
    const float* ca_bk = (const float*)d_in[16];
    const float* ca_wv = (const float*)d_in[17];
    const float* ca_bv = (const float*)d_in[18];
    const float* ca_wo = (const float*)d_in[19];
    const float* ca_bo = (const float*)d_in[20];
    const float* pf_wq = (const float*)d_in[21];
    const float* pf_bq = (const float*)d_in[22];
    const float* pf_wk = (const float*)d_in[23];
    const float* pf_bk = (const float*)d_in[24];
    const float* pf_wv = (const float*)d_in[25];
    const float* pf_bv = (const float*)d_in[26];

    __half *pqT, *psT, *pwq, *pwk, *pwv1, *pwv2, *pcq, *pck, *pcv, *pco;
    __half *pq, *pkt, *pS, *pST, *pv1, *pv2, *px1, *px2, *pq2, *pk2, *pv2fT;
    float *pscores, *pwp, *pmsp, *pw, *pmsum, *ppmid, *pproto, *pqp, *pkp, *pvp, *paw;
    cudaGetSymbolAddress((void**)&pqT, h_qryT);
    cudaGetSymbolAddress((void**)&psT, h_sptT);
    cudaGetSymbolAddress((void**)&pwq, h_wq);
    cudaGetSymbolAddress((void**)&pwk, h_wk);
    cudaGetSymbolAddress((void**)&pwv1, h_wv1);
    cudaGetSymbolAddress((void**)&pwv2, h_wv2);
    cudaGetSymbolAddress((void**)&pcq, h_cawq);
    cudaGetSymbolAddress((void**)&pck, h_cawk);
    cudaGetSymbolAddress((void**)&pcv, h_cawv);
    cudaGetSymbolAddress((void**)&pco, h_cawo);
    cudaGetSymbolAddress((void**)&pq, h_q);
    cudaGetSymbolAddress((void**)&pkt, h_kt);
    cudaGetSymbolAddress((void**)&pscores, g_scores);
    cudaGetSymbolAddress((void**)&pS, h_S);
    cudaGetSymbolAddress((void**)&pST, h_ST);
    cudaGetSymbolAddress((void**)&pv1, h_v1);
    cudaGetSymbolAddress((void**)&pv2, h_v2);
    cudaGetSymbolAddress((void**)&px1, h_x1);
    cudaGetSymbolAddress((void**)&px2, h_x2);
    cudaGetSymbolAddress((void**)&pq2, h_q2);
    cudaGetSymbolAddress((void**)&pk2, h_k2);
    cudaGetSymbolAddress((void**)&pv2fT, h_v2fT);
    cudaGetSymbolAddress((void**)&pwp, g_wp);
    cudaGetSymbolAddress((void**)&pmsp, g_msp);
    cudaGetSymbolAddress((void**)&pw, g_w);
    cudaGetSymbolAddress((void**)&pmsum, g_msum);
    cudaGetSymbolAddress((void**)&ppmid, g_pmid);
    cudaGetSymbolAddress((void**)&pproto, g_proto);
    cudaGetSymbolAddress((void**)&pqp, g_qp);
    cudaGetSymbolAddress((void**)&pkp, g_kp);
    cudaGetSymbolAddress((void**)&pvp, g_vp);
    cudaGetSymbolAddress((void**)&paw, g_aw);

    cudaFuncSetAttribute(hgemm2<true>,  cudaFuncAttributeMaxDynamicSharedMemorySize, SMEM_HG);
    cudaFuncSetAttribute(hgemm2<false>, cudaFuncAttributeMaxDynamicSharedMemorySize, SMEM_HG);

    const long NC   = (long)HWN * CC;     // 2304*512
    const long ND   = (long)HWN * DD;
    const long NN   = (long)HWN * HWN;
    dim3 blk(256);
    const float inv_sqrt_c = 0.044194173824159216f;

    // 0a) all weights -> fp16, one launch
    w2h_all<<<dim3((CC * CC) / 1024, 8), 256>>>(
        w_wq, w_wk, w_wv1, w_wv2, ca_wq, ca_wk, ca_wv, ca_wo,
        pwq, pwk, pwv1, pwv2, pcq, pck, pcv, pco);
    // 0b) qry/spt -> fp16 transposed [n][c]
    tcvt_kernel<<<dim3(HWN / 32, CC / 32, BB), dim3(32, 8)>>>(qry, pqT);
    tcvt_kernel<<<dim3(HWN / 32, CC / 32, BB), dim3(32, 8)>>>(spt, psT);

    // 1+2) q/kt merged: q[n][d] = qryT·wq^T + b ; kt[n][d] = sptT·wk^T + b
    hgemm2<true><<<dim3(1, 18, 2 * BB), blk, SMEM_HG>>>(HWN, DD, CC,
        pqT, CC, NC,  pwq, CC, 0,  pq, DD, ND,  b_wq, 1, nullptr, 1.f, nullptr, 0, 0,
        psT, pwk, pkt, b_wk, nullptr, nullptr);
    // 3) scores1[n][m] = q·kt^T   (M=N=2304,K=64)
    hgemm2<false><<<dim3(18, 18, BB), blk, SMEM_HG>>>(HWN, HWN, DD,
        pq, DD, ND,  pkt, DD, ND,  pscores, HWN, NN,  nullptr, 0, nullptr, 1.f, nullptr, 0, 0,
        nullptr, nullptr, nullptr, nullptr, nullptr, nullptr);
    // 4) softmax -> S fp16 ; transpose -> ST
    softmax_h<<<BB * HWN, 256>>>(pscores, pS);
    th_kernel<<<dim3(HWN / 32, HWN / 32, BB), dim3(32, 8)>>>(pS, pST);
    // 5+6) v1/v2 merged: v1[c][n] = wv1·qry + b ; v2[c][n] = wv2·spt + b (bias per-row c)
    hgemm2<true><<<dim3(18, 4, 2 * BB), blk, SMEM_HG>>>(CC, HWN, CC,
        pwv1, CC, 0,  pqT, CC, NC,  pv1, HWN, (long)CC * HWN,  b_wv1, 2, nullptr, 1.f, nullptr, 0, 0,
        pwv2, psT, pv2, b_wv2, nullptr, nullptr);
    // 7+8) x1/x2 merged  (M=2304,N=512,K=2304)
    // x1[m][c] = gamma1·sum_n S[m][n]·v1[c][n] + qryT[m][c]
    // x2[m][c] = gamma2·sum_n ST[m][n]·v2[c][n] + sptT[m][c]
    hgemm2<true><<<dim3(4, 18, 2 * BB), blk, SMEM_HG>>>(HWN, CC, HWN,
        pS, HWN, NN,  pv1, HWN, (long)CC * HWN,  px1, CC, NC,
        nullptr, 0, gamma1, 1.f, pqT, CC, NC,
        pST, pv2, px2, nullptr, psT, gamma2);
    // 9+10) q2/k2 merged: q2 = x1·ca_wq^T + b ; k2 = x2·ca_wk^T + b  (M=2304,N=512,K=512)
    hgemm2<true><<<dim3(4, 18, 2 * BB), blk, SMEM_HG>>>(HWN, CC, CC,
        px1, CC, NC,  pcq, CC, 0,  pq2, CC, NC,  ca_bq, 1, nullptr, 1.f, nullptr, 0, 0,
        px2, pck, pk2, ca_bk, nullptr, nullptr);
    // 11) v2fT[c][m] = ca_wv·x2^T + b  (M=512,N=2304,K=512), bias per-row c
    hgemm2<true><<<dim3(18, 4, BB), blk, SMEM_HG>>>(CC, HWN, CC,
        pcv, CC, 0,  px2, CC, NC,  pv2fT, HWN, (long)CC * HWN,  ca_bv, 2, nullptr, 1.f, nullptr, 0, 0,
        nullptr, nullptr, nullptr, nullptr, nullptr, nullptr);
    // 12) scores2[n][m] = q2·k2^T /sqrt(C)  (M=N=2304,K=512)
    hgemm2<false><<<dim3(18, 18, BB), blk, SMEM_HG>>>(HWN, HWN, CC,
        pq2, CC, NC,  pk2, CC, NC,  pscores, HWN, NN,  nullptr, 0, nullptr, inv_sqrt_c, nullptr, 0, 0,
        nullptr, nullptr, nullptr, nullptr, nullptr, nullptr);
    // 13) softmax -> S2 fp16 (reuse h_S)
    softmax_h<<<BB * HWN, 256>>>(pscores, pS);
    // 14') two-stage column reduction: w[b][m] = sum_n mask[n]·S2[n][m]
    colw_part<<<dim3(HWN / 256, 18, BB), 128>>>(pS, mask, pwp, pmsp);
    colw_reduce<<<dim3(HWN / 256, BB), 256>>>(pwp, pmsp, pw, pmsum);
    // 15') pmid[b][c] = sum_m w[m]·v2fT[c][m]
    pooledmid_kernel<<<dim3(CC / 8, BB), 256>>>(pw, pv2fT, ppmid);
    // 16') proto = (pmid·ca_wo^T + bo·msum)/(msum+1e-5)
    proto_proj<<<dim3(CC / 8, BB), 256>>>(ppmid, pmsum, ca_wo, ca_bo, pproto);
    // 17) pf projections
    pf_gemv<<<dim3(CC / 8, 3, BB), 256>>>(pproto,
        pf_wq, pf_bq, pf_wk, pf_bk, pf_wv, pf_bv, pqp, pkp, pvp);
    // 18) aw[b] = qp[b]·kp[b]
    aw_kernel<<<BB, 256>>>(pqp, pkp, paw);
    // 19) softmax over batch + weighted sum -> out
    final_kernel<<<1, 512>>>(paw, pvp, (float*)d_out, out_size);
}